// round 15
// baseline (speedup 1.0000x reference)
#include <cuda_runtime.h>
#include <cuda_fp16.h>
#include <cstdint>

#define IN_DIM   64
#define HID      128
#define HID2     256
#define OUT_DIM  64
#define NSTEPS   20
#define NTHREADS 512
#define NWARP    16
#define M_TILE   64
#define KCH      64            // K rows per chunk (4 k16 blocks = 2 pairs)
#define NSLOT    3
#define SLOTU    8192          // u32 per ring slot (max chunk 32 KB)
#define TOTAL_CHUNKS (1 + NSTEPS * 4 * 10 + 2)  // 803

static constexpr float DTC = 1.0f / 20.0f;

// Weights pre-packed (fp16) in b-fragment order:
// [k16pair pk][n8 j][lane(4g+t)][r], r0/r1 = b0/b1 of k16 block 2pk,
// r2/r3 = b0/b1 of block 2pk+1.  uint4 => 16B alignment for cp.async.bulk.
__device__ uint4 g_Wenc4[IN_DIM * HID / 8];
__device__ uint4 g_W14[HID * HID2 / 8];
__device__ uint4 g_W24[HID2 * HID2 / 8];
__device__ uint4 g_W34[HID2 * HID / 8];
__device__ uint4 g_Wdec4[HID * OUT_DIM / 8];

__device__ __forceinline__ uint32_t h2u(__half2 h) {
    return *reinterpret_cast<uint32_t*>(&h);
}
// Single-instruction MUFU.TANH (sm_75+).
__device__ __forceinline__ float fast_tanh(float x) {
    float r;
    asm("tanh.approx.f32 %0, %1;" : "=f"(r) : "f"(x));
    return r;
}
__device__ __forceinline__ void mma16(float c[4], const uint4& a, uint32_t b0,
                                      uint32_t b1) {
    asm("mma.sync.aligned.m16n8k16.row.col.f32.f16.f16.f32 "
        "{%0,%1,%2,%3},{%4,%5,%6,%7},{%8,%9},{%0,%1,%2,%3};"
        : "+f"(c[0]), "+f"(c[1]), "+f"(c[2]), "+f"(c[3])
        : "r"(a.x), "r"(a.y), "r"(a.z), "r"(a.w), "r"(b0), "r"(b1));
}

// ---- mbarrier / named-barrier helpers ----
__device__ __forceinline__ void mbar_init(uint32_t mbar, uint32_t cnt) {
    asm volatile("mbarrier.init.shared.b64 [%0], %1;" ::"r"(mbar), "r"(cnt)
                 : "memory");
}
__device__ __forceinline__ void mbar_arrive(uint32_t mbar) {
    asm volatile("mbarrier.arrive.shared.b64 _, [%0];" ::"r"(mbar) : "memory");
}
__device__ __forceinline__ void mbar_wait(uint32_t mbar, uint32_t parity) {
    asm volatile(
        "{\n\t.reg .pred P;\n\t"
        "W_%=:\n\t"
        "mbarrier.try_wait.parity.acquire.cta.shared::cta.b64 P, [%0], %1;\n\t"
        "@!P bra W_%=;\n\t}" ::"r"(mbar),
        "r"(parity)
        : "memory");
}
__device__ __forceinline__ void stage_bulk(uint32_t dst, const void* src,
                                           uint32_t bytes, uint32_t mbar) {
    asm volatile("mbarrier.arrive.expect_tx.shared.b64 _, [%0], %1;" ::"r"(mbar),
                 "r"(bytes)
                 : "memory");
    asm volatile(
        "cp.async.bulk.shared::cta.global.mbarrier::complete_tx::bytes "
        "[%0], [%1], %2, [%3];" ::"r"(dst),
        "l"(src), "r"(bytes), "r"(mbar)
        : "memory");
}
__device__ __forceinline__ void barsync(int id) {
    asm volatile("bar.sync %0, %1;" ::"r"(id), "r"(256) : "memory");
}

// Global chunk schedule: 0 = encoder, 1..800 = 80 evals x (2 W1 + 4 W2 + 4 W3),
// 801..802 = decoder. Stage into slot idx % NSLOT.
__device__ __forceinline__ void stage_sched(int idx, uint32_t wb_b,
                                            uint32_t mbF) {
    const uint4* src;
    uint32_t bytes;
    if (idx == 0) {
        src = g_Wenc4; bytes = 16384;
    } else if (idx <= 800) {
        int r = (idx - 1) % 10;
        if (r < 2) {
            src = g_W14 + r * 2048; bytes = 32768;
        } else if (r < 6) {
            src = g_W24 + (r - 2) * 2048; bytes = 32768;
        } else {
            src = g_W34 + (r - 6) * 1024; bytes = 16384;
        }
    } else {
        src = g_Wdec4 + (idx - 801) * 512; bytes = 8192;
    }
    int s = idx % NSLOT;
    stage_bulk(wb_b + s * (SLOTU * 4), src, bytes, mbF + s * 8);
}

// C[2][NF][4] = A(group rows, fp16 fragment SMEM, tile stride TS uint4) * W.
// Consumes K/KCH chunks from the CONTINUOUS ring; t0 restages slot s with
// schedule chunk stageIdx (== consumed chunk + NSLOT) after its empty.
// Only a TOP group barrier: callers guarantee write-buffer != read-buffer.
template <int K, int N, int TS>
__device__ __forceinline__ void gemm_core(
    const uint4* __restrict__ Ab4, const uint4* __restrict__ Wb4,
    uint32_t wb_b, float C[2][4][4], int tile0, int nwp, int lane,
    uint32_t mbF, uint32_t mbE, uint32_t& fph, uint32_t& eph, int& slot,
    int& stageIdx, bool t0, int barid) {
    constexpr int NF = N / 64;
    constexpr int N8 = N / 8;
    constexpr int NCH = K / KCH;
#pragma unroll
    for (int mi = 0; mi < 2; mi++)
#pragma unroll
        for (int j = 0; j < NF; j++)
#pragma unroll
            for (int e = 0; e < 4; e++) C[mi][j][e] = 0.0f;

    barsync(barid);  // group's prior epilogue writes visible before A reads
    const uint4* Ap0 = Ab4 + tile0 * TS + lane;
#pragma unroll 1
    for (int ch = 0; ch < NCH; ch++) {
        const int s = slot;
        slot = (slot == NSLOT - 1) ? 0 : slot + 1;
        mbar_wait(mbF + s * 8, (fph >> s) & 1u);
        fph ^= 1u << s;
        const uint4* Ws = Wb4 + s * (SLOTU / 4);
#pragma unroll
        for (int pk = 0; pk < 2; pk++) {
            const int kb0 = ch * 4 + pk * 2;
            uint4 A00 = Ap0[kb0 * 32];
            uint4 A01 = Ap0[(kb0 + 1) * 32];
            uint4 A10 = Ap0[TS + kb0 * 32];
            uint4 A11 = Ap0[TS + (kb0 + 1) * 32];
            uint4 Bv[NF];
#pragma unroll
            for (int j = 0; j < NF; j++)
                Bv[j] = Ws[(pk * N8 + nwp * NF + j) * 32 + lane];
#pragma unroll
            for (int j = 0; j < NF; j++) {
                mma16(C[0][j], A00, Bv[j].x, Bv[j].y);
                mma16(C[1][j], A10, Bv[j].x, Bv[j].y);
            }
#pragma unroll
            for (int j = 0; j < NF; j++) {
                mma16(C[0][j], A01, Bv[j].z, Bv[j].w);
                mma16(C[1][j], A11, Bv[j].z, Bv[j].w);
            }
        }
        __syncwarp();
        if ((threadIdx.x & 31) == 0) mbar_arrive(mbE + s * 8);
        if (t0 && stageIdx < TOTAL_CHUNKS) {
            mbar_wait(mbE + s * 8, (eph >> s) & 1u);
            eph ^= 1u << s;
            stage_sched(stageIdx++, wb_b, mbF);
        }
    }
}

// Pack W (K x N row-major f32) into fp16 b-fragment order (u32 index i).
__device__ __forceinline__ void packW(int i, int N, const float* src,
                                      uint32_t* dst) {
    int N8 = N / 8;
    int perPk = N8 * 128;
    int pk = i / perPk;
    int rem = i - pk * perPk;
    int j = rem >> 7;
    int l = rem & 127;
    int lane = l >> 2, r = l & 3;
    int g = lane >> 2, t = lane & 3;
    int kb = 2 * pk + (r >> 1);
    int k0 = 16 * kb + 2 * t + 8 * (r & 1);
    int n = 8 * j + g;
    dst[i] = h2u(__floats2half2_rn(src[k0 * N + n], src[(k0 + 1) * N + n]));
}

__global__ void prep_kernel(const float* We, const float* W1, const float* W2,
                            const float* W3, const float* Wd) {
    int i = blockIdx.x * blockDim.x + threadIdx.x;
    if (i < IN_DIM * HID / 2) packW(i, HID, We, (uint32_t*)g_Wenc4);
    if (i < HID * HID2 / 2) packW(i, HID2, W1, (uint32_t*)g_W14);
    if (i < HID2 * HID2 / 2) packW(i, HID2, W2, (uint32_t*)g_W24);
    if (i < HID2 * HID / 2) packW(i, HID, W3, (uint32_t*)g_W34);
    if (i < HID * OUT_DIM / 2) packW(i, OUT_DIM, Wd, (uint32_t*)g_Wdec4);
}

__global__ void __launch_bounds__(NTHREADS, 1)
node_kernel(const float* __restrict__ x, const float* __restrict__ benc,
            const float* __restrict__ b1, const float* __restrict__ b2,
            const float* __restrict__ b3, const float* __restrict__ bdec,
            float* __restrict__ out) {
    extern __shared__ uint32_t smemu[];
    uint32_t* HU = smemu;                    // H  [4 tiles][8 kb][128]  16 KB
    uint32_t* ZU = HU + 4096;                // Z  [4][16][128]          32 KB
    uint32_t* Z2U = ZU + 8192;               // Z2 [4][16][128]          32 KB
    uint32_t* WbU = Z2U + 8192;              // ring [3][SLOTU]          96 KB
    float* Bs = (float*)(WbU + NSLOT * SLOTU);  // 832 f32 biases
    uint32_t* Mb = (uint32_t*)(Bs + 832);    // 6 mbarriers (48 B)

    const int tid = threadIdx.x;
    const uint32_t mbF = (uint32_t)__cvta_generic_to_shared(Mb);
    const uint32_t mbE = mbF + NSLOT * 8;
    const uint32_t wb_b = (uint32_t)__cvta_generic_to_shared(WbU);
    const bool t0 = (tid == 0);
    if (t0) {
#pragma unroll
        for (int s = 0; s < NSLOT; s++) {
            mbar_init(mbF + s * 8, 1);
            mbar_init(mbE + s * 8, NWARP);
        }
    }
    if (tid < 256) {
        Bs[tid] = b1[tid];
        Bs[256 + tid] = b2[tid];
    }
    if (tid < 128) {
        Bs[512 + tid] = b3[tid];
        Bs[640 + tid] = benc[tid];
    }
    if (tid < 64) Bs[768 + tid] = bdec[tid];
    __syncthreads();  // mbar init + biases visible to ALL warps
    if ((tid & 31) == 0) {
#pragma unroll
        for (int s = 0; s < NSLOT; s++) mbar_arrive(mbE + s * 8);  // prime empty
    }

    const int row0 = blockIdx.x * M_TILE;
    // x -> H fp16 fragment layout (kb 0..3); thread handles half2 col pairs.
#pragma unroll
    for (int s = 0; s < (M_TILE * IN_DIM / 2) / NTHREADS; s++) {
        int i = s * NTHREADS + tid;
        int r = i >> 5, cp = i & 31;
        int c = 2 * cp;
        int tile = r >> 4, rowin = r & 15;
        int g = rowin & 7, rh = rowin >> 3;
        int kb = c >> 4, kap = c & 15;
        int reg = 2 * (kap >> 3) + rh;
        int tt = (kap & 7) >> 1;
        const float2 xv = *(const float2*)&x[(size_t)(row0 + r) * IN_DIM + c];
        HU[tile * 1024 + kb * 128 + (4 * g + tt) * 4 + reg] =
            h2u(__floats2half2_rn(xv.x, xv.y));
    }
    __syncthreads();  // x staging visible to ALL warps (cross-group)

    int stageIdx = 0;
    uint32_t fph = 0, eph = 0;
    int slot = 0;
    if (t0) {  // prime the continuous ring
#pragma unroll
        for (int i = 0; i < NSLOT; i++) {
            mbar_wait(mbE + i * 8, 0);
            eph ^= 1u << i;
            stage_sched(stageIdx++, wb_b, mbF);
        }
    }

    const int warp = tid >> 5, lane = tid & 31;
    const int mw = warp >> 3, nwp = warp & 7;  // group (M-half) x 8 N-warps
    const int g = lane >> 2, t = lane & 3;
    const int tile0 = mw * 2;
    const int barid = 1 + mw;  // group-scoped named barrier
    const uint4* H4 = (const uint4*)HU;
    const uint4* Z4 = (const uint4*)ZU;
    const uint4* Z24 = (const uint4*)Z2U;
    const uint4* Wb4 = (const uint4*)WbU;

    float C[2][4][4];
    float hreg[2][2][4];  // h state in GEMM3/encoder C-fragment layout
    float acc[2][2][4];   // RK4 accumulator, same layout

    // ---- encoder: tanh(x @ Wenc + benc) -> hreg, H kb0..7 ----
    {
        const int n0 = nwp * 16;  // NF = 2
        gemm_core<IN_DIM, HID, 256>(H4, Wb4, wb_b, C, tile0, nwp, lane, mbF,
                                    mbE, fph, eph, slot, stageIdx, t0, barid);
        barsync(barid);  // encoder writes H over its own read region
#pragma unroll
        for (int mi = 0; mi < 2; mi++)
#pragma unroll
            for (int j = 0; j < 2; j++) {
                int nb = n0 + 8 * j;
                float v0 = fast_tanh(C[mi][j][0] + Bs[640 + nb + 2 * t]);
                float v1 = fast_tanh(C[mi][j][1] + Bs[640 + nb + 2 * t + 1]);
                float v2 = fast_tanh(C[mi][j][2] + Bs[640 + nb + 2 * t]);
                float v3 = fast_tanh(C[mi][j][3] + Bs[640 + nb + 2 * t + 1]);
                hreg[mi][j][0] = v0; hreg[mi][j][1] = v1;
                hreg[mi][j][2] = v2; hreg[mi][j][3] = v3;
                uint2 st = {h2u(__floats2half2_rn(v0, v1)),
                            h2u(__floats2half2_rn(v2, v3))};
                *(uint2*)&HU[(tile0 + mi) * 1024 + (nb >> 4) * 128 + lane * 4 +
                             ((nb & 8) ? 2 : 0)] = st;
            }
    }

#pragma unroll 1
    for (int step = 0; step < NSTEPS; step++) {
#pragma unroll 1
        for (int ev = 0; ev < 4; ev++) {
            // GEMM1: tanh(htmp @ W1 + b1): H -> Z
            {
                const int n0 = nwp * 32;  // NF = 4
                gemm_core<HID, HID2, 256>(H4, Wb4, wb_b, C, tile0, nwp, lane,
                                          mbF, mbE, fph, eph, slot, stageIdx,
                                          t0, barid);
#pragma unroll
                for (int mi = 0; mi < 2; mi++)
#pragma unroll
                    for (int j = 0; j < 4; j++) {
                        int nb = n0 + 8 * j;
                        float b0 = Bs[nb + 2 * t], b1v = Bs[nb + 2 * t + 1];
                        float v0 = fast_tanh(C[mi][j][0] + b0);
                        float v1 = fast_tanh(C[mi][j][1] + b1v);
                        float v2 = fast_tanh(C[mi][j][2] + b0);
                        float v3 = fast_tanh(C[mi][j][3] + b1v);
                        uint2 st = {h2u(__floats2half2_rn(v0, v1)),
                                    h2u(__floats2half2_rn(v2, v3))};
                        *(uint2*)&ZU[(tile0 + mi) * 2048 + (nb >> 4) * 128 +
                                     lane * 4 + ((nb & 8) ? 2 : 0)] = st;
                    }
            }
            // GEMM2: tanh(z1 @ W2 + b2): Z -> Z2
            {
                const int n0 = nwp * 32;  // NF = 4
                gemm_core<HID2, HID2, 512>(Z4, Wb4, wb_b, C, tile0, nwp, lane,
                                           mbF, mbE, fph, eph, slot, stageIdx,
                                           t0, barid);
#pragma unroll
                for (int mi = 0; mi < 2; mi++)
#pragma unroll
                    for (int j = 0; j < 4; j++) {
                        int nb = n0 + 8 * j;
                        float b0 = Bs[256 + nb + 2 * t], b1v = Bs[256 + nb + 2 * t + 1];
                        float v0 = fast_tanh(C[mi][j][0] + b0);
                        float v1 = fast_tanh(C[mi][j][1] + b1v);
                        float v2 = fast_tanh(C[mi][j][2] + b0);
                        float v3 = fast_tanh(C[mi][j][3] + b1v);
                        uint2 st = {h2u(__floats2half2_rn(v0, v1)),
                                    h2u(__floats2half2_rn(v2, v3))};
                        *(uint2*)&Z2U[(tile0 + mi) * 2048 + (nb >> 4) * 128 +
                                      lane * 4 + ((nb & 8) ? 2 : 0)] = st;
                    }
            }
            // GEMM3: k = z2 @ W3 + b3 ; RK4: Z2 -> H, hreg/acc
            {
                const int n0 = nwp * 16;  // NF = 2
                gemm_core<HID2, HID, 512>(Z24, Wb4, wb_b, C, tile0, nwp, lane,
                                          mbF, mbE, fph, eph, slot, stageIdx,
                                          t0, barid);
#pragma unroll
                for (int mi = 0; mi < 2; mi++)
#pragma unroll
                    for (int j = 0; j < 2; j++) {
                        int nb = n0 + 8 * j;
                        float av[4];
#pragma unroll
                        for (int e = 0; e < 4; e++) {
                            float kv = C[mi][j][e] + Bs[512 + nb + 2 * t + (e & 1)];
                            float h = hreg[mi][j][e];
                            if (ev == 0) {
                                acc[mi][j][e] = kv;
                                av[e] = fmaf(0.5f * DTC, kv, h);
                            } else if (ev == 1) {
                                acc[mi][j][e] += 2.0f * kv;
                                av[e] = fmaf(0.5f * DTC, kv, h);
                            } else if (ev == 2) {
                                acc[mi][j][e] += 2.0f * kv;
                                av[e] = fmaf(DTC, kv, h);
                            } else {
                                av[e] = fmaf(DTC / 6.0f, acc[mi][j][e] + kv, h);
                                hreg[mi][j][e] = av[e];
                            }
                        }
                        uint2 st = {h2u(__floats2half2_rn(av[0], av[1])),
                                    h2u(__floats2half2_rn(av[2], av[3]))};
                        *(uint2*)&HU[(tile0 + mi) * 1024 + (nb >> 4) * 128 +
                                     lane * 4 + ((nb & 8) ? 2 : 0)] = st;
                    }
            }
        }
    }

    // ---- decoder: hT @ Wdec + bdec -> out ----
    {
        const int n0 = nwp * 8;  // NF = 1
        gemm_core<HID, OUT_DIM, 256>(H4, Wb4, wb_b, C, tile0, nwp, lane, mbF,
                                     mbE, fph, eph, slot, stageIdx, t0, barid);
#pragma unroll
        for (int mi = 0; mi < 2; mi++) {
            int rr0 = (tile0 + mi) * 16 + g;
            float b0 = Bs[768 + n0 + 2 * t], b1v = Bs[768 + n0 + 2 * t + 1];
            float2 o0 = make_float2(C[mi][0][0] + b0, C[mi][0][1] + b1v);
            float2 o1 = make_float2(C[mi][0][2] + b0, C[mi][0][3] + b1v);
            *(float2*)&out[(size_t)(row0 + rr0) * OUT_DIM + n0 + 2 * t] = o0;
            *(float2*)&out[(size_t)(row0 + rr0 + 8) * OUT_DIM + n0 + 2 * t] = o1;
        }
    }
}

static constexpr int SMEM_BYTES =
    (4096 + 8192 + 8192 + NSLOT * SLOTU) * 4 + 832 * 4 + 64;  // 184,896 B

extern "C" void kernel_launch(void* const* d_in, const int* in_sizes, int n_in,
                              void* d_out, int out_size) {
    const float* x    = (const float*)d_in[0];
    const float* Wenc = (const float*)d_in[1];
    const float* benc = (const float*)d_in[2];
    const float* W1   = (const float*)d_in[3];
    const float* b1   = (const float*)d_in[4];
    const float* W2   = (const float*)d_in[5];
    const float* b2   = (const float*)d_in[6];
    const float* W3   = (const float*)d_in[7];
    const float* b3   = (const float*)d_in[8];
    const float* Wdec = (const float*)d_in[9];
    const float* bdec = (const float*)d_in[10];
    float* out = (float*)d_out;

    const int batch = in_sizes[0] / IN_DIM;  // 65536
    const int grid  = batch / M_TILE;        // 1024

    cudaFuncSetAttribute(node_kernel, cudaFuncAttributeMaxDynamicSharedMemorySize,
                         SMEM_BYTES);

    prep_kernel<<<128, 256>>>(Wenc, W1, W2, W3, Wdec);  // covers 32768 u32 max
    node_kernel<<<grid, NTHREADS, SMEM_BYTES>>>(x, benc, b1, b2, b3, bdec, out);
}

// round 17
// speedup vs baseline: 1.5172x; 1.5172x over previous
#include <cuda_runtime.h>
#include <cuda_fp16.h>
#include <cstdint>

#define IN_DIM   64
#define HID      128
#define HID2     256
#define OUT_DIM  64
#define NSTEPS   20
#define NTHREADS 512
#define NWARP    16
#define M_TILE   64
#define KCH      64            // K rows per chunk (4 k16 blocks = 2 pairs)
#define NSLOT    3
#define SLOTU    8192          // u32 per ring slot (max chunk 32 KB)
#define AF_TILE_U 2048         // u32 per m16 tile in Af (16 kb * 128)

static constexpr float DTC = 1.0f / 20.0f;

// Weights pre-packed (fp16) in b-fragment order:
// [k16pair pk][n8 j][lane(4g+t)][r], r0/r1 = b0/b1 of k16 block 2pk,
// r2/r3 = b0/b1 of block 2pk+1.  uint4 => 16B alignment for cp.async.bulk.
__device__ uint4 g_Wenc4[IN_DIM * HID / 8];
__device__ uint4 g_W14[HID * HID2 / 8];
__device__ uint4 g_W24[HID2 * HID2 / 8];
__device__ uint4 g_W34[HID2 * HID / 8];
__device__ uint4 g_Wdec4[HID * OUT_DIM / 8];

__device__ __forceinline__ uint32_t h2u(__half2 h) {
    return *reinterpret_cast<uint32_t*>(&h);
}
// Single-instruction MUFU.TANH (sm_75+).
__device__ __forceinline__ float fast_tanh(float x) {
    float r;
    asm("tanh.approx.f32 %0, %1;" : "=f"(r) : "f"(x));
    return r;
}
__device__ __forceinline__ void mma16(float c[4], const uint4& a, uint32_t b0,
                                      uint32_t b1) {
    asm("mma.sync.aligned.m16n8k16.row.col.f32.f16.f16.f32 "
        "{%0,%1,%2,%3},{%4,%5,%6,%7},{%8,%9},{%0,%1,%2,%3};"
        : "+f"(c[0]), "+f"(c[1]), "+f"(c[2]), "+f"(c[3])
        : "r"(a.x), "r"(a.y), "r"(a.z), "r"(a.w), "r"(b0), "r"(b1));
}

// ---- mbarrier / named-barrier helpers ----
__device__ __forceinline__ void mbar_init(uint32_t mbar, uint32_t cnt) {
    asm volatile("mbarrier.init.shared.b64 [%0], %1;" ::"r"(mbar), "r"(cnt)
                 : "memory");
}
__device__ __forceinline__ void mbar_arrive(uint32_t mbar) {
    asm volatile("mbarrier.arrive.shared.b64 _, [%0];" ::"r"(mbar) : "memory");
}
__device__ __forceinline__ void mbar_wait(uint32_t mbar, uint32_t parity) {
    asm volatile(
        "{\n\t.reg .pred P;\n\t"
        "W_%=:\n\t"
        "mbarrier.try_wait.parity.acquire.cta.shared::cta.b64 P, [%0], %1;\n\t"
        "@!P bra W_%=;\n\t}" ::"r"(mbar),
        "r"(parity)
        : "memory");
}
__device__ __forceinline__ void stage_bulk(uint32_t dst, const void* src,
                                           uint32_t bytes, uint32_t mbar) {
    asm volatile("mbarrier.arrive.expect_tx.shared.b64 _, [%0], %1;" ::"r"(mbar),
                 "r"(bytes)
                 : "memory");
    asm volatile(
        "cp.async.bulk.shared::cta.global.mbarrier::complete_tx::bytes "
        "[%0], [%1], %2, [%3];" ::"r"(dst),
        "l"(src), "r"(bytes), "r"(mbar)
        : "memory");
}
__device__ __forceinline__ void barsync(int id) {
    asm volatile("bar.sync %0, %1;" ::"r"(id), "r"(256) : "memory");
}

// C[2][NF][4] = A(group-half rows, fp16 fragment SMEM) * W(K x N, fp16).
// This GEMM's first min(NSLOT, NCH) chunks were PRE-STAGED by the previous
// gemm_core's exit (or by main for the encoder). In-loop staging covers
// chunks beyond NSLOT. On exit, t0 pre-stages the NEXT GEMM's first nxPre
// chunks (nxCHU4 uint4 each, from nxWg) into the freed slots — overlapping
// the bulk-copy latency with the 15 other warps' epilogues.
// INVARIANT: nxPre >= min(NSLOT, NCH_next); in-loop staging covers the rest.
template <int K, int N>
__device__ __forceinline__ void gemm_core(
    const uint4* __restrict__ Wg, const uint4* __restrict__ Af4,
    const uint4* __restrict__ Wb4, uint32_t wb_b, float C[2][4][4], int tile0,
    int nwp, int lane, uint32_t mbF, uint32_t mbE, uint32_t& fph,
    uint32_t& eph, int& slot, bool t0, int barid, const uint4* nxWg,
    int nxPre, int nxCHU4) {
    constexpr int NF = N / 64;
    constexpr int N8 = N / 8;
    constexpr int NCH = K / KCH;
    constexpr uint32_t CHU4 = 8 * N;       // uint4 per chunk
    constexpr uint32_t CHB = CHU4 * 16;    // bytes per chunk
#pragma unroll
    for (int mi = 0; mi < 2; mi++)
#pragma unroll
        for (int j = 0; j < NF; j++)
#pragma unroll
            for (int e = 0; e < 4; e++) C[mi][j][e] = 0.0f;

    barsync(barid);  // group's prior epilogue Af writes visible to its warps
    const uint4* Ap0 = Af4 + tile0 * (AF_TILE_U / 4) + lane;
#pragma unroll 1
    for (int ch = 0; ch < NCH; ch++) {
        const int s = slot;
        slot = (slot == NSLOT - 1) ? 0 : slot + 1;
        mbar_wait(mbF + s * 8, (fph >> s) & 1u);
        fph ^= 1u << s;
        const uint4* Ws = Wb4 + s * (SLOTU / 4);
#pragma unroll
        for (int pk = 0; pk < 2; pk++) {
            const int kb0 = ch * 4 + pk * 2;
            uint4 A00 = Ap0[kb0 * 32];
            uint4 A01 = Ap0[(kb0 + 1) * 32];
            uint4 A10 = Ap0[512 + kb0 * 32];
            uint4 A11 = Ap0[512 + (kb0 + 1) * 32];
            uint4 Bv[NF];
#pragma unroll
            for (int j = 0; j < NF; j++)
                Bv[j] = Ws[(pk * N8 + nwp * NF + j) * 32 + lane];
#pragma unroll
            for (int j = 0; j < NF; j++) {
                mma16(C[0][j], A00, Bv[j].x, Bv[j].y);
                mma16(C[1][j], A10, Bv[j].x, Bv[j].y);
            }
#pragma unroll
            for (int j = 0; j < NF; j++) {
                mma16(C[0][j], A01, Bv[j].z, Bv[j].w);
                mma16(C[1][j], A11, Bv[j].z, Bv[j].w);
            }
        }
        __syncwarp();
        if ((threadIdx.x & 31) == 0) mbar_arrive(mbE + s * 8);
        if (t0 && ch + NSLOT < NCH) {
            mbar_wait(mbE + s * 8, (eph >> s) & 1u);
            eph ^= 1u << s;
            stage_bulk(wb_b + s * (SLOTU * 4), Wg + (ch + NSLOT) * CHU4, CHB,
                       mbF + s * 8);
        }
    }
    barsync(barid);  // group's A reads done before its epilogue rewrites Af
    if (t0) {        // pre-stage NEXT GEMM's leading chunks (overlaps epilogue)
#pragma unroll 1
        for (int i = 0; i < nxPre; i++) {
            int s2 = slot + i;
            if (s2 >= NSLOT) s2 -= NSLOT;
            mbar_wait(mbE + s2 * 8, (eph >> s2) & 1u);
            eph ^= 1u << s2;
            stage_bulk(wb_b + s2 * (SLOTU * 4), nxWg + i * nxCHU4,
                       (uint32_t)nxCHU4 * 16u, mbF + s2 * 8);
        }
    }
}

// Pack W (K x N row-major f32) into fp16 b-fragment order (u32 index i).
__device__ __forceinline__ void packW(int i, int N, const float* src,
                                      uint32_t* dst) {
    int N8 = N / 8;
    int perPk = N8 * 128;
    int pk = i / perPk;
    int rem = i - pk * perPk;
    int j = rem >> 7;
    int l = rem & 127;
    int lane = l >> 2, r = l & 3;
    int g = lane >> 2, t = lane & 3;
    int kb = 2 * pk + (r >> 1);
    int k0 = 16 * kb + 2 * t + 8 * (r & 1);
    int n = 8 * j + g;
    dst[i] = h2u(__floats2half2_rn(src[k0 * N + n], src[(k0 + 1) * N + n]));
}

__global__ void prep_kernel(const float* We, const float* W1, const float* W2,
                            const float* W3, const float* Wd) {
    int i = blockIdx.x * blockDim.x + threadIdx.x;
    if (i < IN_DIM * HID / 2) packW(i, HID, We, (uint32_t*)g_Wenc4);
    if (i < HID * HID2 / 2) packW(i, HID2, W1, (uint32_t*)g_W14);
    if (i < HID2 * HID2 / 2) packW(i, HID2, W2, (uint32_t*)g_W24);
    if (i < HID2 * HID / 2) packW(i, HID, W3, (uint32_t*)g_W34);
    if (i < HID * OUT_DIM / 2) packW(i, OUT_DIM, Wd, (uint32_t*)g_Wdec4);
}

__global__ void __launch_bounds__(NTHREADS, 1)
node_kernel(const float* __restrict__ x, const float* __restrict__ benc,
            const float* __restrict__ b1, const float* __restrict__ b2,
            const float* __restrict__ b3, const float* __restrict__ bdec,
            float* __restrict__ out) {
    extern __shared__ uint32_t smemu[];
    uint32_t* AfU = smemu;                          // [4][16][32][4] u32 (32 KB)
    uint32_t* WbU = AfU + 4 * AF_TILE_U;            // [3][SLOTU] (96 KB)
    float* Bs = (float*)(WbU + NSLOT * SLOTU);      // 832 f32 biases
    uint32_t* Mb = (uint32_t*)(Bs + 832);           // 6 mbarriers (48 B)

    const int tid = threadIdx.x;
    const uint32_t mbF = (uint32_t)__cvta_generic_to_shared(Mb);
    const uint32_t mbE = mbF + NSLOT * 8;
    const uint32_t wb_b = (uint32_t)__cvta_generic_to_shared(WbU);
    const bool t0 = (tid == 0);
    if (t0) {
#pragma unroll
        for (int s = 0; s < NSLOT; s++) {
            mbar_init(mbF + s * 8, 1);
            mbar_init(mbE + s * 8, NWARP);
        }
    }
    if (tid < 256) {
        Bs[tid] = b1[tid];
        Bs[256 + tid] = b2[tid];
    }
    if (tid < 128) {
        Bs[512 + tid] = b3[tid];
        Bs[640 + tid] = benc[tid];
    }
    if (tid < 64) Bs[768 + tid] = bdec[tid];
    __syncthreads();  // one-time: mbar init + biases visible to ALL warps
    if ((tid & 31) == 0) {
#pragma unroll
        for (int s = 0; s < NSLOT; s++) mbar_arrive(mbE + s * 8);  // prime empty
    }

    const int row0 = blockIdx.x * M_TILE;
    // x -> Af fp16 fragment layout (once); thread handles half2 col pairs.
#pragma unroll
    for (int s = 0; s < (M_TILE * IN_DIM / 2) / NTHREADS; s++) {
        int i = s * NTHREADS + tid;
        int r = i >> 5, cp = i & 31;
        int c = 2 * cp;
        int tile = r >> 4, rowin = r & 15;
        int g = rowin & 7, rh = rowin >> 3;
        int kb = c >> 4, kap = c & 15;
        int reg = 2 * (kap >> 3) + rh;
        int tt = (kap & 7) >> 1;
        const float2 xv = *(const float2*)&x[(size_t)(row0 + r) * IN_DIM + c];
        AfU[tile * AF_TILE_U + kb * 128 + (4 * g + tt) * 4 + reg] =
            h2u(__floats2half2_rn(xv.x, xv.y));
    }
    __syncthreads();  // one-time: x staging visible to ALL warps (cross-group)

    uint32_t fph = 0, eph = 0;
    int slot = 0;
    if (t0) {  // pre-stage encoder's single chunk
        mbar_wait(mbE, 0);
        eph ^= 1u;
        stage_bulk(wb_b, g_Wenc4, 16384, mbF);
    }

    const int warp = tid >> 5, lane = tid & 31;
    const int mw = warp >> 3, nwp = warp & 7;  // group (M-half) x 8 N-warps
    const int g = lane >> 2, t = lane & 3;
    const int tile0 = mw * 2;
    const int barid = 1 + mw;  // group-scoped named barrier
    const uint4* Af4 = (const uint4*)AfU;
    const uint4* Wb4 = (const uint4*)WbU;

    float C[2][4][4];
    float hreg[2][2][4];  // h state in GEMM3/encoder C-fragment layout
    float acc[2][2][4];   // RK4 accumulator, same layout

    // ---- encoder: tanh(x @ Wenc + benc) -> hreg, Af kb 0..7 ----
    {
        const int n0 = nwp * 16;  // NF = 2
        gemm_core<IN_DIM, HID>(g_Wenc4, Af4, Wb4, wb_b, C, tile0, nwp, lane,
                               mbF, mbE, fph, eph, slot, t0, barid,
                               g_W14, 2, 2048);  // next: G1 (2 chunks, 32 KB)
#pragma unroll
        for (int mi = 0; mi < 2; mi++)
#pragma unroll
            for (int j = 0; j < 2; j++) {
                int nb = n0 + 8 * j;
                float v0 = fast_tanh(C[mi][j][0] + Bs[640 + nb + 2 * t]);
                float v1 = fast_tanh(C[mi][j][1] + Bs[640 + nb + 2 * t + 1]);
                float v2 = fast_tanh(C[mi][j][2] + Bs[640 + nb + 2 * t]);
                float v3 = fast_tanh(C[mi][j][3] + Bs[640 + nb + 2 * t + 1]);
                hreg[mi][j][0] = v0; hreg[mi][j][1] = v1;
                hreg[mi][j][2] = v2; hreg[mi][j][3] = v3;
                uint2 st = {h2u(__floats2half2_rn(v0, v1)),
                            h2u(__floats2half2_rn(v2, v3))};
                *(uint2*)&AfU[(tile0 + mi) * AF_TILE_U + (nb >> 4) * 128 +
                              lane * 4 + ((nb & 8) ? 2 : 0)] = st;
            }
    }

#pragma unroll 1
    for (int step = 0; step < NSTEPS; step++) {
#pragma unroll 1
        for (int ev = 0; ev < 4; ev++) {
            // GEMM1: tanh(htmp @ W1 + b1) -> Af kb 0..15
            {
                const int n0 = nwp * 32;  // NF = 4
                gemm_core<HID, HID2>(g_W14, Af4, Wb4, wb_b, C, tile0, nwp, lane,
                                     mbF, mbE, fph, eph, slot, t0, barid,
                                     g_W24, 3, 2048);  // next: G2
#pragma unroll
                for (int mi = 0; mi < 2; mi++)
#pragma unroll
                    for (int j = 0; j < 4; j++) {
                        int nb = n0 + 8 * j;
                        float b0 = Bs[nb + 2 * t], b1v = Bs[nb + 2 * t + 1];
                        float v0 = fast_tanh(C[mi][j][0] + b0);
                        float v1 = fast_tanh(C[mi][j][1] + b1v);
                        float v2 = fast_tanh(C[mi][j][2] + b0);
                        float v3 = fast_tanh(C[mi][j][3] + b1v);
                        uint2 st = {h2u(__floats2half2_rn(v0, v1)),
                                    h2u(__floats2half2_rn(v2, v3))};
                        *(uint2*)&AfU[(tile0 + mi) * AF_TILE_U + (nb >> 4) * 128 +
                                      lane * 4 + ((nb & 8) ? 2 : 0)] = st;
                    }
            }
            // GEMM2: tanh(z1 @ W2 + b2) -> Af kb 0..15
            {
                const int n0 = nwp * 32;  // NF = 4
                gemm_core<HID2, HID2>(g_W24, Af4, Wb4, wb_b, C, tile0, nwp,
                                      lane, mbF, mbE, fph, eph, slot, t0, barid,
                                      g_W34, 3, 1024);  // next: G3 (16 KB ch)
#pragma unroll
                for (int mi = 0; mi < 2; mi++)
#pragma unroll
                    for (int j = 0; j < 4; j++) {
                        int nb = n0 + 8 * j;
                        float b0 = Bs[256 + nb + 2 * t], b1v = Bs[256 + nb + 2 * t + 1];
                        float v0 = fast_tanh(C[mi][j][0] + b0);
                        float v1 = fast_tanh(C[mi][j][1] + b1v);
                        float v2 = fast_tanh(C[mi][j][2] + b0);
                        float v3 = fast_tanh(C[mi][j][3] + b1v);
                        uint2 st = {h2u(__floats2half2_rn(v0, v1)),
                                    h2u(__floats2half2_rn(v2, v3))};
                        *(uint2*)&AfU[(tile0 + mi) * AF_TILE_U + (nb >> 4) * 128 +
                                      lane * 4 + ((nb & 8) ? 2 : 0)] = st;
                    }
            }
            // GEMM3: k = z2 @ W3 + b3 ; RK4 -> Af kb 0..7, hreg/acc
            {
                const int n0 = nwp * 16;  // NF = 2
                const bool last = (step == NSTEPS - 1) && (ev == 3);
                const uint4* nx = last ? g_Wdec4 : g_W14;
                const int nxPre = 2;               // both G1 and decoder: 2 chunks
                const int nxC = last ? 512 : 2048; // decoder chunk = 8 KB
                gemm_core<HID2, HID>(g_W34, Af4, Wb4, wb_b, C, tile0, nwp, lane,
                                     mbF, mbE, fph, eph, slot, t0, barid,
                                     nx, nxPre, nxC);
#pragma unroll
                for (int mi = 0; mi < 2; mi++)
#pragma unroll
                    for (int j = 0; j < 2; j++) {
                        int nb = n0 + 8 * j;
                        float av[4];
#pragma unroll
                        for (int e = 0; e < 4; e++) {
                            float kv = C[mi][j][e] + Bs[512 + nb + 2 * t + (e & 1)];
                            float h = hreg[mi][j][e];
                            if (ev == 0) {
                                acc[mi][j][e] = kv;
                                av[e] = fmaf(0.5f * DTC, kv, h);
                            } else if (ev == 1) {
                                acc[mi][j][e] += 2.0f * kv;
                                av[e] = fmaf(0.5f * DTC, kv, h);
                            } else if (ev == 2) {
                                acc[mi][j][e] += 2.0f * kv;
                                av[e] = fmaf(DTC, kv, h);
                            } else {
                                av[e] = fmaf(DTC / 6.0f, acc[mi][j][e] + kv, h);
                                hreg[mi][j][e] = av[e];
                            }
                        }
                        uint2 st = {h2u(__floats2half2_rn(av[0], av[1])),
                                    h2u(__floats2half2_rn(av[2], av[3]))};
                        *(uint2*)&AfU[(tile0 + mi) * AF_TILE_U + (nb >> 4) * 128 +
                                      lane * 4 + ((nb & 8) ? 2 : 0)] = st;
                    }
            }
        }
    }

    // ---- decoder: hT @ Wdec + bdec -> out ----
    {
        const int n0 = nwp * 8;  // NF = 1
        gemm_core<HID, OUT_DIM>(g_Wdec4, Af4, Wb4, wb_b, C, tile0, nwp, lane,
                                mbF, mbE, fph, eph, slot, t0, barid,
                                g_Wdec4, 0, 0);  // no next
#pragma unroll
        for (int mi = 0; mi < 2; mi++) {
            int rr0 = (tile0 + mi) * 16 + g;
            float b0 = Bs[768 + n0 + 2 * t], b1v = Bs[768 + n0 + 2 * t + 1];
            float2 o0 = make_float2(C[mi][0][0] + b0, C[mi][0][1] + b1v);
            float2 o1 = make_float2(C[mi][0][2] + b0, C[mi][0][3] + b1v);
            *(float2*)&out[(size_t)(row0 + rr0) * OUT_DIM + n0 + 2 * t] = o0;
            *(float2*)&out[(size_t)(row0 + rr0 + 8) * OUT_DIM + n0 + 2 * t] = o1;
        }
    }
}

static constexpr int SMEM_BYTES =
    (4 * AF_TILE_U + NSLOT * SLOTU) * 4 + 832 * 4 + 64;  // 134,528 B

extern "C" void kernel_launch(void* const* d_in, const int* in_sizes, int n_in,
                              void* d_out, int out_size) {
    const float* x    = (const float*)d_in[0];
    const float* Wenc = (const float*)d_in[1];
    const float* benc = (const float*)d_in[2];
    const float* W1   = (const float*)d_in[3];
    const float* b1   = (const float*)d_in[4];
    const float* W2   = (const float*)d_in[5];
    const float* b2   = (const float*)d_in[6];
    const float* W3   = (const float*)d_in[7];
    const float* b3   = (const float*)d_in[8];
    const float* Wdec = (const float*)d_in[9];
    const float* bdec = (const float*)d_in[10];
    float* out = (float*)d_out;

    const int batch = in_sizes[0] / IN_DIM;  // 65536
    const int grid  = batch / M_TILE;        // 1024

    cudaFuncSetAttribute(node_kernel, cudaFuncAttributeMaxDynamicSharedMemorySize,
                         SMEM_BYTES);

    prep_kernel<<<128, 256>>>(Wenc, W1, W2, W3, Wdec);  // covers 32768 u32 max
    node_kernel<<<grid, NTHREADS, SMEM_BYTES>>>(x, benc, b1, b2, b3, bdec, out);
}